// round 6
// baseline (speedup 1.0000x reference)
#include <cuda_runtime.h>

#define N_NODES 100000
#define IN_DIM 512
#define HIDDEN 16
#define OUT_DIM 64
#define E_CAP 3300000

// ---------------- device scratch (no allocations allowed) ----------------
__device__ __align__(16) float g_z[(size_t)N_NODES * HIDDEN];  // (x@W1)*dinv[src]
__device__ __align__(16) float g_h[(size_t)N_NODES * HIDDEN];  // h1*dinv (layer-2 msgs)
__device__ float g_dinv[N_NODES];
__device__ int g_cnt[N_NODES];
__device__ int g_off[N_NODES + 1];
__device__ int g_cur[N_NODES];
__device__ int g_slot[E_CAP];

// ---------------- helpers ----------------
__device__ __forceinline__ unsigned long long fma2(unsigned long long a,
                                                   unsigned long long b,
                                                   unsigned long long c) {
    unsigned long long d;
    asm("fma.rn.f32x2 %0, %1, %2, %3;" : "=l"(d) : "l"(a), "l"(b), "l"(c));
    return d;
}
__device__ __forceinline__ unsigned long long dup2(float v) {
    unsigned long long d;
    asm("mov.b64 %0, {%1, %2};" : "=l"(d) : "f"(v), "f"(v));
    return d;
}

// ---------------- CSR build ----------------

__global__ void k_zero() {
    int i = blockIdx.x * blockDim.x + threadIdx.x;
    if (i < N_NODES) g_cnt[i] = 0;
}

__global__ void k_count(const int* __restrict__ dst, int E4, int E) {
    int t = blockIdx.x * blockDim.x + threadIdx.x;
    if (t < E4) {
        int4 d = __ldg((const int4*)dst + t);
        atomicAdd(&g_cnt[d.x], 1);
        atomicAdd(&g_cnt[d.y], 1);
        atomicAdd(&g_cnt[d.z], 1);
        atomicAdd(&g_cnt[d.w], 1);
    } else if (t == E4) {
        for (int e = E4 * 4; e < E; e++) atomicAdd(&g_cnt[__ldg(dst + e)], 1);
    }
}

// single-block exclusive scan of g_cnt -> g_off/g_cur; also dinv = rsqrt(cnt+1)
__global__ __launch_bounds__(1024) void k_scan() {
    __shared__ int sc[1024];
    const int CH = 98;  // 1024*98 >= 100000
    int t = threadIdx.x;
    int base = t * CH;
    int tot = 0;
    for (int i = 0; i < CH; i++) {
        int idx = base + i;
        if (idx < N_NODES) tot += g_cnt[idx];
    }
    sc[t] = tot;
    __syncthreads();
    for (int d = 1; d < 1024; d <<= 1) {
        int v = (t >= d) ? sc[t - d] : 0;
        __syncthreads();
        sc[t] += v;
        __syncthreads();
    }
    int run = sc[t] - tot;  // exclusive prefix
    for (int i = 0; i < CH; i++) {
        int idx = base + i;
        if (idx < N_NODES) {
            int c = g_cnt[idx];
            g_off[idx] = run;
            g_cur[idx] = run;
            g_dinv[idx] = rsqrtf((float)(c + 1));  // +1 self loop
            run += c;
        }
    }
    if (t == 1023) g_off[N_NODES] = sc[1023];
}

__global__ void k_fill(const int* __restrict__ src, const int* __restrict__ dst,
                       int E4, int E) {
    int t = blockIdx.x * blockDim.x + threadIdx.x;
    if (t < E4) {
        int4 s = __ldg((const int4*)src + t);
        int4 d = __ldg((const int4*)dst + t);
        int p;
        p = atomicAdd(&g_cur[d.x], 1); g_slot[p] = s.x;
        p = atomicAdd(&g_cur[d.y], 1); g_slot[p] = s.y;
        p = atomicAdd(&g_cur[d.z], 1); g_slot[p] = s.z;
        p = atomicAdd(&g_cur[d.w], 1); g_slot[p] = s.w;
    } else if (t == E4) {
        for (int e = E4 * 4; e < E; e++) {
            int p = atomicAdd(&g_cur[__ldg(dst + e)], 1);
            g_slot[p] = __ldg(src + e);
        }
    }
}

// ---------------- layer 1 transform (R4-proven) ----------------
// z = (x @ W1) * dinv[row].  128 threads/block, 4 rows/thread (strided by 128).
__global__ __launch_bounds__(128) void k_gemm1(const float* __restrict__ x,
                                               const float* __restrict__ W1) {
    __shared__ __align__(16) float ws[IN_DIM * HIDDEN];  // 32 KB
    {
        const float4* w4 = (const float4*)W1;
        float4* s4 = (float4*)ws;
#pragma unroll
        for (int i = 0; i < (IN_DIM * HIDDEN / 4) / 128; i++)
            s4[threadIdx.x + i * 128] = w4[threadIdx.x + i * 128];
    }
    __syncthreads();

    long long base = (long long)blockIdx.x * 512 + threadIdx.x;
    long long r[4];
    const float4* xp[4];
#pragma unroll
    for (int i = 0; i < 4; i++) {
        r[i] = base + i * 128;
        long long ra = (r[i] < N_NODES) ? r[i] : 0;
        xp[i] = (const float4*)(x + ra * IN_DIM);
    }

    unsigned long long acc[4][8];
#pragma unroll
    for (int i = 0; i < 4; i++)
#pragma unroll
        for (int c = 0; c < 8; c++) acc[i][c] = 0ull;

    const ulonglong2* wsp = (const ulonglong2*)ws;

#pragma unroll 1
    for (int q = 0; q < IN_DIM / 4; q += 2) {
        float4 xa[4], xb[4];
#pragma unroll
        for (int i = 0; i < 4; i++) xa[i] = xp[i][q];
#pragma unroll
        for (int i = 0; i < 4; i++) xb[i] = xp[i][q + 1];

#pragma unroll
        for (int j = 0; j < 4; j++) {
            int k = q * 4 + j;
            ulonglong2 w0 = wsp[k * 4 + 0];
            ulonglong2 w1 = wsp[k * 4 + 1];
            ulonglong2 w2 = wsp[k * 4 + 2];
            ulonglong2 w3 = wsp[k * 4 + 3];
#pragma unroll
            for (int i = 0; i < 4; i++) {
                unsigned long long d = dup2(((const float*)&xa[i])[j]);
                acc[i][0] = fma2(d, w0.x, acc[i][0]);
                acc[i][1] = fma2(d, w0.y, acc[i][1]);
                acc[i][2] = fma2(d, w1.x, acc[i][2]);
                acc[i][3] = fma2(d, w1.y, acc[i][3]);
                acc[i][4] = fma2(d, w2.x, acc[i][4]);
                acc[i][5] = fma2(d, w2.y, acc[i][5]);
                acc[i][6] = fma2(d, w3.x, acc[i][6]);
                acc[i][7] = fma2(d, w3.y, acc[i][7]);
            }
        }
#pragma unroll
        for (int j = 0; j < 4; j++) {
            int k = (q + 1) * 4 + j;
            ulonglong2 w0 = wsp[k * 4 + 0];
            ulonglong2 w1 = wsp[k * 4 + 1];
            ulonglong2 w2 = wsp[k * 4 + 2];
            ulonglong2 w3 = wsp[k * 4 + 3];
#pragma unroll
            for (int i = 0; i < 4; i++) {
                unsigned long long d = dup2(((const float*)&xb[i])[j]);
                acc[i][0] = fma2(d, w0.x, acc[i][0]);
                acc[i][1] = fma2(d, w0.y, acc[i][1]);
                acc[i][2] = fma2(d, w1.x, acc[i][2]);
                acc[i][3] = fma2(d, w1.y, acc[i][3]);
                acc[i][4] = fma2(d, w2.x, acc[i][4]);
                acc[i][5] = fma2(d, w2.y, acc[i][5]);
                acc[i][6] = fma2(d, w3.x, acc[i][6]);
                acc[i][7] = fma2(d, w3.y, acc[i][7]);
            }
        }
    }

#pragma unroll
    for (int i = 0; i < 4; i++) {
        if (r[i] < N_NODES) {
            float dv = g_dinv[r[i]];
            float2* zo = (float2*)(g_z + r[i] * HIDDEN);
#pragma unroll
            for (int c = 0; c < 8; c++) {
                float2 p = *(float2*)&acc[i][c];
                p.x *= dv; p.y *= dv;
                zo[c] = p;
            }
        }
    }
}

// ---------------- layer 1 gather + pointwise (fused) ----------------
// warp = 8 nodes x 4 feature-quads. acc = sum of z[s] over incoming edges;
// h1s = relu((acc + z[n])*dinv + b1) * dinv   -> g_h
__global__ __launch_bounds__(256) void k_gather1(const float* __restrict__ b1) {
    int gw = (blockIdx.x * 256 + threadIdx.x) >> 5;
    int lane = threadIdx.x & 31;
    int ns = lane >> 2, cg = lane & 3;
    int n = gw * 8 + ns;
    if (n >= N_NODES) return;  // whole warp exits together (N % 8 == 0)

    float4 bb = __ldg((const float4*)b1 + cg);
    int e0 = g_off[n], e1 = g_off[n + 1];
    float4 acc = make_float4(0.f, 0.f, 0.f, 0.f);
#pragma unroll 2
    for (int e = e0; e < e1; e++) {
        int s = __ldg(g_slot + e);
        float4 v = __ldg((const float4*)(g_z + (size_t)s * HIDDEN) + cg);
        acc.x += v.x; acc.y += v.y; acc.z += v.z; acc.w += v.w;
    }
    float di = g_dinv[n];
    float4 zn = *((const float4*)(g_z + (size_t)n * HIDDEN) + cg);
    float4 r;
    r.x = fmaxf(fmaf(acc.x + zn.x, di, bb.x), 0.f) * di;
    r.y = fmaxf(fmaf(acc.y + zn.y, di, bb.y), 0.f) * di;
    r.z = fmaxf(fmaf(acc.z + zn.z, di, bb.z), 0.f) * di;
    r.w = fmaxf(fmaf(acc.w + zn.w, di, bb.w), 0.f) * di;
    *((float4*)(g_h + (size_t)n * HIDDEN) + cg) = r;
}

// ---------------- layer 2 gather + GEMM2 (fused) ----------------
// warp = 8 nodes x 4 quads. hk = (gather + h[n]) * dinv; exchange across 4
// lanes -> full hk[16]; each lane computes its 16 output cols from smem W2.
__global__ __launch_bounds__(256) void k_gather2(const float* __restrict__ W2,
                                                 const float* __restrict__ b2,
                                                 float* __restrict__ out) {
    __shared__ __align__(16) float ws[HIDDEN * OUT_DIM];  // 4 KB
    ((float4*)ws)[threadIdx.x] = ((const float4*)W2)[threadIdx.x];  // 256 float4
    __syncthreads();

    int gw = (blockIdx.x * 256 + threadIdx.x) >> 5;
    int lane = threadIdx.x & 31;
    int ns = lane >> 2, cg = lane & 3;
    int n = gw * 8 + ns;
    if (n >= N_NODES) return;  // whole warp exits together

    int e0 = g_off[n], e1 = g_off[n + 1];
    float4 acc = make_float4(0.f, 0.f, 0.f, 0.f);
#pragma unroll 2
    for (int e = e0; e < e1; e++) {
        int s = __ldg(g_slot + e);
        float4 v = __ldg((const float4*)(g_h + (size_t)s * HIDDEN) + cg);
        acc.x += v.x; acc.y += v.y; acc.z += v.z; acc.w += v.w;
    }
    float di = g_dinv[n];
    float4 hn = *((const float4*)(g_h + (size_t)n * HIDDEN) + cg);
    float4 my;
    my.x = (acc.x + hn.x) * di;
    my.y = (acc.y + hn.y) * di;
    my.z = (acc.z + hn.z) * di;
    my.w = (acc.w + hn.w) * di;

    // exchange quads across the node's 4 lanes -> full hk[16]
    float hk[16];
    int lbase = lane & ~3;
#pragma unroll
    for (int q = 0; q < 4; q++) {
        int sl = lbase | q;
        hk[q * 4 + 0] = __shfl_sync(0xffffffffu, my.x, sl);
        hk[q * 4 + 1] = __shfl_sync(0xffffffffu, my.y, sl);
        hk[q * 4 + 2] = __shfl_sync(0xffffffffu, my.z, sl);
        hk[q * 4 + 3] = __shfl_sync(0xffffffffu, my.w, sl);
    }

    float4 o[4];
#pragma unroll
    for (int q = 0; q < 4; q++) o[q] = make_float4(0.f, 0.f, 0.f, 0.f);
#pragma unroll
    for (int k = 0; k < HIDDEN; k++) {
        float xv = hk[k];
        const float4* wr = (const float4*)(ws + k * OUT_DIM + cg * 16);
#pragma unroll
        for (int q = 0; q < 4; q++) {
            float4 w = wr[q];
            o[q].x = fmaf(xv, w.x, o[q].x);
            o[q].y = fmaf(xv, w.y, o[q].y);
            o[q].z = fmaf(xv, w.z, o[q].z);
            o[q].w = fmaf(xv, w.w, o[q].w);
        }
    }

    float4* O = (float4*)(out + (size_t)n * OUT_DIM) + cg * 4;
    const float4* bb = (const float4*)b2 + cg * 4;
#pragma unroll
    for (int q = 0; q < 4; q++) {
        float4 b = __ldg(bb + q);
        O[q] = make_float4(o[q].x + b.x, o[q].y + b.y, o[q].z + b.z, o[q].w + b.w);
    }
}

// ---------------- launch ----------------
extern "C" void kernel_launch(void* const* d_in, const int* in_sizes, int n_in,
                              void* d_out, int out_size) {
    const float* x = nullptr;
    const float* W1 = nullptr;
    const float* b1 = nullptr;
    const float* W2 = nullptr;
    const float* b2 = nullptr;
    const int* ei = nullptr;
    int E = 0;
    for (int i = 0; i < n_in; i++) {
        long long sz = in_sizes[i];
        if (sz == (long long)N_NODES * IN_DIM)      x  = (const float*)d_in[i];
        else if (sz == IN_DIM * HIDDEN)             W1 = (const float*)d_in[i];
        else if (sz == HIDDEN)                      b1 = (const float*)d_in[i];
        else if (sz == HIDDEN * OUT_DIM)            W2 = (const float*)d_in[i];
        else if (sz == OUT_DIM)                     b2 = (const float*)d_in[i];
        else { ei = (const int*)d_in[i]; E = (int)(sz / 2); }
    }
    const int* src = ei;
    const int* dst = ei + E;
    float* out = (float*)d_out;

    const int TB = 256;
    int E4 = E / 4;
    int grid_n  = (N_NODES + TB - 1) / TB;
    int grid_e4 = (E4 + 1 + TB - 1) / TB;
    int grid_g1 = (N_NODES + 511) / 512;           // 196
    int grid_gw = (N_NODES / 8 + 7) / 8;           // 12500 warps -> 1563 blocks

    k_zero<<<grid_n, TB>>>();
    k_count<<<grid_e4, TB>>>(dst, E4, E);
    k_scan<<<1, 1024>>>();
    k_fill<<<grid_e4, TB>>>(src, dst, E4, E);
    k_gemm1<<<grid_g1, 128>>>(x, W1);
    k_gather1<<<grid_gw, TB>>>(b1);
    k_gather2<<<grid_gw, TB>>>(W2, b2, out);
}

// round 7
// speedup vs baseline: 1.9174x; 1.9174x over previous
#include <cuda_runtime.h>

#define N_NODES 100000
#define IN_DIM 512
#define HIDDEN 16
#define OUT_DIM 64
#define E_CAP 3300000
#define NBLK 391              // ceil(100000/256)

// ---------------- device scratch (no allocations allowed) ----------------
__device__ __align__(16) float g_z[(size_t)N_NODES * HIDDEN];  // (x@W1)*dinv[src]
__device__ __align__(16) float g_h[(size_t)N_NODES * HIDDEN];  // h1*dinv (layer-2 msgs)
__device__ float g_dinv[N_NODES];
__device__ int g_cnt[N_NODES];
__device__ int g_off[N_NODES + 1];
__device__ int g_cur[N_NODES];
__device__ int g_slot[E_CAP];
__device__ int g_bsum[NBLK];
__device__ int g_boff[NBLK];

// ---------------- helpers ----------------
__device__ __forceinline__ unsigned long long fma2(unsigned long long a,
                                                   unsigned long long b,
                                                   unsigned long long c) {
    unsigned long long d;
    asm("fma.rn.f32x2 %0, %1, %2, %3;" : "=l"(d) : "l"(a), "l"(b), "l"(c));
    return d;
}
__device__ __forceinline__ unsigned long long dup2(float v) {
    unsigned long long d;
    asm("mov.b64 %0, {%1, %2};" : "=l"(d) : "f"(v), "f"(v));
    return d;
}

// ---------------- CSR build ----------------

__global__ void k_zero() {
    int i = blockIdx.x * blockDim.x + threadIdx.x;
    if (i < N_NODES) g_cnt[i] = 0;
}

__global__ void k_count(const int* __restrict__ dst, int E4, int E) {
    int t = blockIdx.x * blockDim.x + threadIdx.x;
    if (t < E4) {
        int4 d = __ldg((const int4*)dst + t);
        atomicAdd(&g_cnt[d.x], 1);
        atomicAdd(&g_cnt[d.y], 1);
        atomicAdd(&g_cnt[d.z], 1);
        atomicAdd(&g_cnt[d.w], 1);
    } else if (t == E4) {
        for (int e = E4 * 4; e < E; e++) atomicAdd(&g_cnt[__ldg(dst + e)], 1);
    }
}

__global__ void k_dinv() {
    int i = blockIdx.x * blockDim.x + threadIdx.x;
    if (i < N_NODES) g_dinv[i] = rsqrtf((float)(g_cnt[i] + 1));  // +1 self loop
}

// per-block sum of 256 counts
__global__ __launch_bounds__(256) void k_bsum() {
    __shared__ int sw[8];
    int idx = blockIdx.x * 256 + threadIdx.x;
    int v = (idx < N_NODES) ? g_cnt[idx] : 0;
#pragma unroll
    for (int m = 16; m; m >>= 1) v += __shfl_xor_sync(0xffffffffu, v, m);
    if ((threadIdx.x & 31) == 0) sw[threadIdx.x >> 5] = v;
    __syncthreads();
    if (threadIdx.x < 8) {
        int s = sw[threadIdx.x];
#pragma unroll
        for (int m = 4; m; m >>= 1) s += __shfl_xor_sync(0xffu, s, m);
        if (threadIdx.x == 0) g_bsum[blockIdx.x] = s;
    }
}

// single-block exclusive scan of 391 block sums (tiny)
__global__ __launch_bounds__(512) void k_bscan() {
    __shared__ int sc[512];
    int t = threadIdx.x;
    int v = (t < NBLK) ? g_bsum[t] : 0;
    sc[t] = v;
    __syncthreads();
#pragma unroll
    for (int d = 1; d < 512; d <<= 1) {
        int u = (t >= d) ? sc[t - d] : 0;
        __syncthreads();
        sc[t] += u;
        __syncthreads();
    }
    if (t < NBLK) g_boff[t] = sc[t] - v;  // exclusive
}

// block-wide exclusive scan of counts + add block offset -> g_off, g_cur
__global__ __launch_bounds__(256) void k_expand() {
    __shared__ int sw[8];
    int idx = blockIdx.x * 256 + threadIdx.x;
    int lane = threadIdx.x & 31, w = threadIdx.x >> 5;
    int v = (idx < N_NODES) ? g_cnt[idx] : 0;
    // warp inclusive scan
    int incl = v;
#pragma unroll
    for (int d = 1; d < 32; d <<= 1) {
        int u = __shfl_up_sync(0xffffffffu, incl, d);
        if (lane >= d) incl += u;
    }
    if (lane == 31) sw[w] = incl;
    __syncthreads();
    if (threadIdx.x < 8) {
        int s = sw[threadIdx.x];
        int si = s;
#pragma unroll
        for (int d = 1; d < 8; d <<= 1) {
            int u = __shfl_up_sync(0xffu, si, d);
            if (threadIdx.x >= d) si += u;
        }
        sw[threadIdx.x] = si - s;  // exclusive warp offsets
    }
    __syncthreads();
    int off = g_boff[blockIdx.x] + sw[w] + (incl - v);
    if (idx < N_NODES) {
        g_off[idx] = off;
        g_cur[idx] = off;
        if (idx == N_NODES - 1) g_off[N_NODES] = off + v;
    }
}

__global__ void k_fill(const int* __restrict__ src, const int* __restrict__ dst,
                       int E4, int E) {
    int t = blockIdx.x * blockDim.x + threadIdx.x;
    if (t < E4) {
        int4 s = __ldg((const int4*)src + t);
        int4 d = __ldg((const int4*)dst + t);
        int p;
        p = atomicAdd(&g_cur[d.x], 1); g_slot[p] = s.x;
        p = atomicAdd(&g_cur[d.y], 1); g_slot[p] = s.y;
        p = atomicAdd(&g_cur[d.z], 1); g_slot[p] = s.z;
        p = atomicAdd(&g_cur[d.w], 1); g_slot[p] = s.w;
    } else if (t == E4) {
        for (int e = E4 * 4; e < E; e++) {
            int p = atomicAdd(&g_cur[__ldg(dst + e)], 1);
            g_slot[p] = __ldg(src + e);
        }
    }
}

// ---------------- layer 1 transform (R4-proven) ----------------
__global__ __launch_bounds__(128) void k_gemm1(const float* __restrict__ x,
                                               const float* __restrict__ W1) {
    __shared__ __align__(16) float ws[IN_DIM * HIDDEN];  // 32 KB
    {
        const float4* w4 = (const float4*)W1;
        float4* s4 = (float4*)ws;
#pragma unroll
        for (int i = 0; i < (IN_DIM * HIDDEN / 4) / 128; i++)
            s4[threadIdx.x + i * 128] = w4[threadIdx.x + i * 128];
    }
    __syncthreads();

    long long base = (long long)blockIdx.x * 512 + threadIdx.x;
    long long r[4];
    const float4* xp[4];
#pragma unroll
    for (int i = 0; i < 4; i++) {
        r[i] = base + i * 128;
        long long ra = (r[i] < N_NODES) ? r[i] : 0;
        xp[i] = (const float4*)(x + ra * IN_DIM);
    }

    unsigned long long acc[4][8];
#pragma unroll
    for (int i = 0; i < 4; i++)
#pragma unroll
        for (int c = 0; c < 8; c++) acc[i][c] = 0ull;

    const ulonglong2* wsp = (const ulonglong2*)ws;

#pragma unroll 1
    for (int q = 0; q < IN_DIM / 4; q += 2) {
        float4 xa[4], xb[4];
#pragma unroll
        for (int i = 0; i < 4; i++) xa[i] = xp[i][q];
#pragma unroll
        for (int i = 0; i < 4; i++) xb[i] = xp[i][q + 1];

#pragma unroll
        for (int j = 0; j < 4; j++) {
            int k = q * 4 + j;
            ulonglong2 w0 = wsp[k * 4 + 0];
            ulonglong2 w1 = wsp[k * 4 + 1];
            ulonglong2 w2 = wsp[k * 4 + 2];
            ulonglong2 w3 = wsp[k * 4 + 3];
#pragma unroll
            for (int i = 0; i < 4; i++) {
                unsigned long long d = dup2(((const float*)&xa[i])[j]);
                acc[i][0] = fma2(d, w0.x, acc[i][0]);
                acc[i][1] = fma2(d, w0.y, acc[i][1]);
                acc[i][2] = fma2(d, w1.x, acc[i][2]);
                acc[i][3] = fma2(d, w1.y, acc[i][3]);
                acc[i][4] = fma2(d, w2.x, acc[i][4]);
                acc[i][5] = fma2(d, w2.y, acc[i][5]);
                acc[i][6] = fma2(d, w3.x, acc[i][6]);
                acc[i][7] = fma2(d, w3.y, acc[i][7]);
            }
        }
#pragma unroll
        for (int j = 0; j < 4; j++) {
            int k = (q + 1) * 4 + j;
            ulonglong2 w0 = wsp[k * 4 + 0];
            ulonglong2 w1 = wsp[k * 4 + 1];
            ulonglong2 w2 = wsp[k * 4 + 2];
            ulonglong2 w3 = wsp[k * 4 + 3];
#pragma unroll
            for (int i = 0; i < 4; i++) {
                unsigned long long d = dup2(((const float*)&xb[i])[j]);
                acc[i][0] = fma2(d, w0.x, acc[i][0]);
                acc[i][1] = fma2(d, w0.y, acc[i][1]);
                acc[i][2] = fma2(d, w1.x, acc[i][2]);
                acc[i][3] = fma2(d, w1.y, acc[i][3]);
                acc[i][4] = fma2(d, w2.x, acc[i][4]);
                acc[i][5] = fma2(d, w2.y, acc[i][5]);
                acc[i][6] = fma2(d, w3.x, acc[i][6]);
                acc[i][7] = fma2(d, w3.y, acc[i][7]);
            }
        }
    }

#pragma unroll
    for (int i = 0; i < 4; i++) {
        if (r[i] < N_NODES) {
            float dv = g_dinv[r[i]];
            float2* zo = (float2*)(g_z + r[i] * HIDDEN);
#pragma unroll
            for (int c = 0; c < 8; c++) {
                float2 p = *(float2*)&acc[i][c];
                p.x *= dv; p.y *= dv;
                zo[c] = p;
            }
        }
    }
}

// ---------------- layer 1 gather + pointwise (fused) ----------------
// warp = 4 nodes x 2 edge-lanes x 4 quads.
__global__ __launch_bounds__(256) void k_gather1(const float* __restrict__ b1) {
    int gw = (blockIdx.x * 256 + threadIdx.x) >> 5;
    int lane = threadIdx.x & 31;
    int ns = lane >> 3, ep = (lane >> 2) & 1, cg = lane & 3;
    int n = gw * 4 + ns;                    // N % 4 == 0 -> always valid
    if (n >= N_NODES) return;

    int e0 = g_off[n], e1 = g_off[n + 1];
    float4 acc = make_float4(0.f, 0.f, 0.f, 0.f);
    for (int e = e0 + ep; e < e1; e += 2) {
        int s = __ldg(g_slot + e);
        float4 v = __ldg((const float4*)(g_z + (size_t)s * HIDDEN) + cg);
        acc.x += v.x; acc.y += v.y; acc.z += v.z; acc.w += v.w;
    }
    // combine the two edge-lanes
    acc.x += __shfl_xor_sync(0xffffffffu, acc.x, 4);
    acc.y += __shfl_xor_sync(0xffffffffu, acc.y, 4);
    acc.z += __shfl_xor_sync(0xffffffffu, acc.z, 4);
    acc.w += __shfl_xor_sync(0xffffffffu, acc.w, 4);

    if (ep == 0) {
        float di = g_dinv[n];
        float4 bb = __ldg((const float4*)b1 + cg);
        float4 zn = *((const float4*)(g_z + (size_t)n * HIDDEN) + cg);
        float4 r;
        r.x = fmaxf(fmaf(acc.x + zn.x, di, bb.x), 0.f) * di;
        r.y = fmaxf(fmaf(acc.y + zn.y, di, bb.y), 0.f) * di;
        r.z = fmaxf(fmaf(acc.z + zn.z, di, bb.z), 0.f) * di;
        r.w = fmaxf(fmaf(acc.w + zn.w, di, bb.w), 0.f) * di;
        *((float4*)(g_h + (size_t)n * HIDDEN) + cg) = r;
    }
}

// ---------------- layer 2 gather + GEMM2 (fused) ----------------
// warp = 4 nodes x 2 edge-lanes x 4 quads; GEMM uses all 8 lanes per node
// (each lane computes 8 of the 64 output cols).
__global__ __launch_bounds__(256) void k_gather2(const float* __restrict__ W2,
                                                 const float* __restrict__ b2,
                                                 float* __restrict__ out) {
    __shared__ __align__(16) float ws[HIDDEN * OUT_DIM];  // 4 KB
    ((float4*)ws)[threadIdx.x] = ((const float4*)W2)[threadIdx.x];  // 256 float4
    __syncthreads();

    int gw = (blockIdx.x * 256 + threadIdx.x) >> 5;
    int lane = threadIdx.x & 31;
    int ns = lane >> 3, ep = (lane >> 2) & 1, cg = lane & 3;
    int n = gw * 4 + ns;
    if (n >= N_NODES) return;

    int e0 = g_off[n], e1 = g_off[n + 1];
    float4 acc = make_float4(0.f, 0.f, 0.f, 0.f);
    for (int e = e0 + ep; e < e1; e += 2) {
        int s = __ldg(g_slot + e);
        float4 v = __ldg((const float4*)(g_h + (size_t)s * HIDDEN) + cg);
        acc.x += v.x; acc.y += v.y; acc.z += v.z; acc.w += v.w;
    }
    acc.x += __shfl_xor_sync(0xffffffffu, acc.x, 4);
    acc.y += __shfl_xor_sync(0xffffffffu, acc.y, 4);
    acc.z += __shfl_xor_sync(0xffffffffu, acc.z, 4);
    acc.w += __shfl_xor_sync(0xffffffffu, acc.w, 4);

    float di = g_dinv[n];
    float4 hn = *((const float4*)(g_h + (size_t)n * HIDDEN) + cg);
    float4 my;
    my.x = (acc.x + hn.x) * di;
    my.y = (acc.y + hn.y) * di;
    my.z = (acc.z + hn.z) * di;
    my.w = (acc.w + hn.w) * di;

    // broadcast hk[16] within the node's 8-lane group (take from ep=0, cg=q)
    float hk[16];
    int base8 = lane & ~7;
#pragma unroll
    for (int q = 0; q < 4; q++) {
        int sl = base8 + q;
        hk[q * 4 + 0] = __shfl_sync(0xffffffffu, my.x, sl);
        hk[q * 4 + 1] = __shfl_sync(0xffffffffu, my.y, sl);
        hk[q * 4 + 2] = __shfl_sync(0xffffffffu, my.z, sl);
        hk[q * 4 + 3] = __shfl_sync(0xffffffffu, my.w, sl);
    }

    // each of the 8 lanes computes 8 output columns
    int oc = lane & 7;
    float4 o0 = make_float4(0.f, 0.f, 0.f, 0.f);
    float4 o1 = make_float4(0.f, 0.f, 0.f, 0.f);
#pragma unroll
    for (int k = 0; k < HIDDEN; k++) {
        float xv = hk[k];
        const float4* wr = (const float4*)(ws + k * OUT_DIM + oc * 8);
        float4 wa = wr[0], wb = wr[1];
        o0.x = fmaf(xv, wa.x, o0.x); o0.y = fmaf(xv, wa.y, o0.y);
        o0.z = fmaf(xv, wa.z, o0.z); o0.w = fmaf(xv, wa.w, o0.w);
        o1.x = fmaf(xv, wb.x, o1.x); o1.y = fmaf(xv, wb.y, o1.y);
        o1.z = fmaf(xv, wb.z, o1.z); o1.w = fmaf(xv, wb.w, o1.w);
    }

    const float4* bb = (const float4*)b2 + oc * 2;
    float4 ba = __ldg(bb), bc = __ldg(bb + 1);
    float4* O = (float4*)(out + (size_t)n * OUT_DIM) + oc * 2;
    O[0] = make_float4(o0.x + ba.x, o0.y + ba.y, o0.z + ba.z, o0.w + ba.w);
    O[1] = make_float4(o1.x + bc.x, o1.y + bc.y, o1.z + bc.z, o1.w + bc.w);
}

// ---------------- launch ----------------
extern "C" void kernel_launch(void* const* d_in, const int* in_sizes, int n_in,
                              void* d_out, int out_size) {
    const float* x = nullptr;
    const float* W1 = nullptr;
    const float* b1 = nullptr;
    const float* W2 = nullptr;
    const float* b2 = nullptr;
    const int* ei = nullptr;
    int E = 0;
    for (int i = 0; i < n_in; i++) {
        long long sz = in_sizes[i];
        if (sz == (long long)N_NODES * IN_DIM)      x  = (const float*)d_in[i];
        else if (sz == IN_DIM * HIDDEN)             W1 = (const float*)d_in[i];
        else if (sz == HIDDEN)                      b1 = (const float*)d_in[i];
        else if (sz == HIDDEN * OUT_DIM)            W2 = (const float*)d_in[i];
        else if (sz == OUT_DIM)                     b2 = (const float*)d_in[i];
        else { ei = (const int*)d_in[i]; E = (int)(sz / 2); }
    }
    const int* src = ei;
    const int* dst = ei + E;
    float* out = (float*)d_out;

    const int TB = 256;
    int E4 = E / 4;
    int grid_n  = (N_NODES + TB - 1) / TB;       // 391
    int grid_e4 = (E4 + 1 + TB - 1) / TB;
    int grid_g1 = (N_NODES + 511) / 512;         // 196
    int grid_gw = (N_NODES / 4 * 32 + TB - 1) / TB;  // 25000 warps -> 3125 blocks

    k_zero<<<grid_n, TB>>>();
    k_count<<<grid_e4, TB>>>(dst, E4, E);
    k_dinv<<<grid_n, TB>>>();
    k_gemm1<<<grid_g1, 128>>>(x, W1);      // 4th launch (profiled)
    k_bsum<<<NBLK, TB>>>();
    k_bscan<<<1, 512>>>();
    k_expand<<<NBLK, TB>>>();
    k_fill<<<grid_e4, TB>>>(src, dst, E4, E);
    k_gather1<<<grid_gw, TB>>>(b1);
    k_gather2<<<grid_gw, TB>>>(W2, b2, out);
}

// round 9
// speedup vs baseline: 2.1900x; 1.1422x over previous
#include <cuda_runtime.h>

#define N_NODES 100000
#define IN_DIM 512
#define HIDDEN 16
#define OUT_DIM 64
#define E_CAP 3300000
#define NBLK 391              // ceil(100000/256)

// ---------------- device scratch (no allocations allowed) ----------------
__device__ __align__(16) float g_z[(size_t)N_NODES * HIDDEN];  // (x@W1)*dinv[src]
__device__ __align__(16) float g_h[(size_t)N_NODES * HIDDEN];  // h1*dinv (layer-2 msgs)
__device__ float g_dinv[N_NODES];
__device__ int g_cnt[N_NODES];
__device__ int g_off[N_NODES + 1];
__device__ int g_cur[N_NODES];
__device__ int g_slot[E_CAP];
__device__ int g_bsum[NBLK];
__device__ int g_boff[NBLK];

// ---------------- helpers ----------------
__device__ __forceinline__ unsigned long long fma2(unsigned long long a,
                                                   unsigned long long b,
                                                   unsigned long long c) {
    unsigned long long d;
    asm("fma.rn.f32x2 %0, %1, %2, %3;" : "=l"(d) : "l"(a), "l"(b), "l"(c));
    return d;
}
__device__ __forceinline__ unsigned long long dup2(float v) {
    unsigned long long d;
    asm("mov.b64 %0, {%1, %2};" : "=l"(d) : "f"(v), "f"(v));
    return d;
}

// ---------------- CSR build ----------------

__global__ void k_zero() {
    int i = blockIdx.x * blockDim.x + threadIdx.x;
    if (i < N_NODES) g_cnt[i] = 0;
}

__global__ void k_count(const int* __restrict__ dst, int E4, int E) {
    int t = blockIdx.x * blockDim.x + threadIdx.x;
    if (t < E4) {
        int4 d = __ldg((const int4*)dst + t);
        atomicAdd(&g_cnt[d.x], 1);
        atomicAdd(&g_cnt[d.y], 1);
        atomicAdd(&g_cnt[d.z], 1);
        atomicAdd(&g_cnt[d.w], 1);
    } else if (t == E4) {
        for (int e = E4 * 4; e < E; e++) atomicAdd(&g_cnt[__ldg(dst + e)], 1);
    }
}

__global__ void k_dinv() {
    int i = blockIdx.x * blockDim.x + threadIdx.x;
    if (i < N_NODES) g_dinv[i] = rsqrtf((float)(g_cnt[i] + 1));  // +1 self loop
}

// per-block sum of 256 counts
__global__ __launch_bounds__(256) void k_bsum() {
    __shared__ int sw[8];
    int idx = blockIdx.x * 256 + threadIdx.x;
    int v = (idx < N_NODES) ? g_cnt[idx] : 0;
#pragma unroll
    for (int m = 16; m; m >>= 1) v += __shfl_xor_sync(0xffffffffu, v, m);
    if ((threadIdx.x & 31) == 0) sw[threadIdx.x >> 5] = v;
    __syncthreads();
    if (threadIdx.x < 8) {
        int s = sw[threadIdx.x];
#pragma unroll
        for (int m = 4; m; m >>= 1) s += __shfl_xor_sync(0xffu, s, m);
        if (threadIdx.x == 0) g_bsum[blockIdx.x] = s;
    }
}

// single-block exclusive scan of 391 block sums (tiny)
__global__ __launch_bounds__(512) void k_bscan() {
    __shared__ int sc[512];
    int t = threadIdx.x;
    int v = (t < NBLK) ? g_bsum[t] : 0;
    sc[t] = v;
    __syncthreads();
#pragma unroll
    for (int d = 1; d < 512; d <<= 1) {
        int u = (t >= d) ? sc[t - d] : 0;
        __syncthreads();
        sc[t] += u;
        __syncthreads();
    }
    if (t < NBLK) g_boff[t] = sc[t] - v;  // exclusive
}

// block-wide exclusive scan of counts + add block offset -> g_off, g_cur
__global__ __launch_bounds__(256) void k_expand() {
    __shared__ int sw[8];
    int idx = blockIdx.x * 256 + threadIdx.x;
    int lane = threadIdx.x & 31, w = threadIdx.x >> 5;
    int v = (idx < N_NODES) ? g_cnt[idx] : 0;
    int incl = v;
#pragma unroll
    for (int d = 1; d < 32; d <<= 1) {
        int u = __shfl_up_sync(0xffffffffu, incl, d);
        if (lane >= d) incl += u;
    }
    if (lane == 31) sw[w] = incl;
    __syncthreads();
    if (threadIdx.x < 8) {
        int s = sw[threadIdx.x];
        int si = s;
#pragma unroll
        for (int d = 1; d < 8; d <<= 1) {
            int u = __shfl_up_sync(0xffu, si, d);
            if (threadIdx.x >= d) si += u;
        }
        sw[threadIdx.x] = si - s;  // exclusive warp offsets
    }
    __syncthreads();
    int off = g_boff[blockIdx.x] + sw[w] + (incl - v);
    if (idx < N_NODES) {
        g_off[idx] = off;
        g_cur[idx] = off;
        if (idx == N_NODES - 1) g_off[N_NODES] = off + v;
    }
}

__global__ void k_fill(const int* __restrict__ src, const int* __restrict__ dst,
                       int E4, int E) {
    int t = blockIdx.x * blockDim.x + threadIdx.x;
    if (t < E4) {
        int4 s = __ldg((const int4*)src + t);
        int4 d = __ldg((const int4*)dst + t);
        int p;
        p = atomicAdd(&g_cur[d.x], 1); g_slot[p] = s.x;
        p = atomicAdd(&g_cur[d.y], 1); g_slot[p] = s.y;
        p = atomicAdd(&g_cur[d.z], 1); g_slot[p] = s.z;
        p = atomicAdd(&g_cur[d.w], 1); g_slot[p] = s.w;
    } else if (t == E4) {
        for (int e = E4 * 4; e < E; e++) {
            int p = atomicAdd(&g_cur[__ldg(dst + e)], 1);
            g_slot[p] = __ldg(src + e);
        }
    }
}

// ---------------- layer 1 transform: smem-staged x ----------------
// Block = 128 threads <-> 256 rows (2 rows/thread). K staged in 32-float
// chunks. Load: warp reads 4 rows x 128B contiguous -> 4 lines/LDG.
// xs padded to 36 floats/row -> conflict-free float4 LDS phases.
// Weights staged per chunk (2KB, warp-uniform broadcast reads).
__global__ __launch_bounds__(128) void k_gemm1(const float* __restrict__ x,
                                               const float* __restrict__ W1) {
    __shared__ __align__(16) float xs[256 * 36];  // 36 KB
    __shared__ __align__(16) float wst[32 * 16];  // 2 KB

    int t = threadIdx.x;
    int lrow = t >> 3, lcol = t & 7;
    long long rb = (long long)blockIdx.x * 256;

    unsigned long long acc0[8], acc1[8];
#pragma unroll
    for (int i = 0; i < 8; i++) { acc0[i] = 0ull; acc1[i] = 0ull; }

    const ulonglong2* wsp = (const ulonglong2*)wst;
    const float4* w4 = (const float4*)W1;

#pragma unroll 1
    for (int st = 0; st < 16; st++) {
        int k0 = st * 32;
        __syncthreads();  // xs/wst reuse barrier
        // stage weights: W1[k0..k0+31][0..15] = 128 float4, one per thread
        ((float4*)wst)[t] = __ldg(w4 + k0 * 4 + t);
        // stage x tile: 256 rows x 32 floats
#pragma unroll
        for (int i = 0; i < 16; i++) {
            int row = i * 16 + lrow;
            long long gr = rb + row;
            if (gr >= N_NODES) gr = 0;
            float4 v = __ldg((const float4*)(x + gr * IN_DIM + k0) + lcol);
            *(float4*)(xs + row * 36 + lcol * 4) = v;
        }
        __syncthreads();

        const float4* xr0 = (const float4*)(xs + t * 36);
        const float4* xr1 = (const float4*)(xs + (t + 128) * 36);
#pragma unroll
        for (int hc = 0; hc < 2; hc++) {
            float4 v0[4], v1[4];
#pragma unroll
            for (int j = 0; j < 4; j++) { v0[j] = xr0[hc * 4 + j]; v1[j] = xr1[hc * 4 + j]; }
#pragma unroll
            for (int j = 0; j < 4; j++) {
#pragma unroll
                for (int jj = 0; jj < 4; jj++) {
                    int kl = hc * 16 + j * 4 + jj;
                    ulonglong2 w0 = wsp[kl * 4 + 0];
                    ulonglong2 w1 = wsp[kl * 4 + 1];
                    ulonglong2 w2 = wsp[kl * 4 + 2];
                    ulonglong2 w3 = wsp[kl * 4 + 3];
                    unsigned long long d0 = dup2(((const float*)&v0[j])[jj]);
                    unsigned long long d1 = dup2(((const float*)&v1[j])[jj]);
                    acc0[0] = fma2(d0, w0.x, acc0[0]);
                    acc0[1] = fma2(d0, w0.y, acc0[1]);
                    acc0[2] = fma2(d0, w1.x, acc0[2]);
                    acc0[3] = fma2(d0, w1.y, acc0[3]);
                    acc0[4] = fma2(d0, w2.x, acc0[4]);
                    acc0[5] = fma2(d0, w2.y, acc0[5]);
                    acc0[6] = fma2(d0, w3.x, acc0[6]);
                    acc0[7] = fma2(d0, w3.y, acc0[7]);
                    acc1[0] = fma2(d1, w0.x, acc1[0]);
                    acc1[1] = fma2(d1, w0.y, acc1[1]);
                    acc1[2] = fma2(d1, w1.x, acc1[2]);
                    acc1[3] = fma2(d1, w1.y, acc1[3]);
                    acc1[4] = fma2(d1, w2.x, acc1[4]);
                    acc1[5] = fma2(d1, w2.y, acc1[5]);
                    acc1[6] = fma2(d1, w3.x, acc1[6]);
                    acc1[7] = fma2(d1, w3.y, acc1[7]);
                }
            }
        }
    }

    long long r0 = rb + t;
    long long r1 = rb + t + 128;
    if (r0 < N_NODES) {
        float dv = g_dinv[r0];
        float2* zo = (float2*)(g_z + r0 * HIDDEN);
#pragma unroll
        for (int c = 0; c < 8; c++) {
            float2 p = *(float2*)&acc0[c];
            p.x *= dv; p.y *= dv;
            zo[c] = p;
        }
    }
    if (r1 < N_NODES) {
        float dv = g_dinv[r1];
        float2* zo = (float2*)(g_z + r1 * HIDDEN);
#pragma unroll
        for (int c = 0; c < 8; c++) {
            float2 p = *(float2*)&acc1[c];
            p.x *= dv; p.y *= dv;
            zo[c] = p;
        }
    }
}

// ---------------- layer 1 gather + pointwise (fused) ----------------
// warp = 4 nodes x 2 edge-lanes x 4 quads.
__global__ __launch_bounds__(256) void k_gather1(const float* __restrict__ b1) {
    int gw = (blockIdx.x * 256 + threadIdx.x) >> 5;
    int lane = threadIdx.x & 31;
    int ns = lane >> 3, ep = (lane >> 2) & 1, cg = lane & 3;
    int n = gw * 4 + ns;                    // N % 4 == 0 -> always valid
    if (n >= N_NODES) return;

    int e0 = g_off[n], e1 = g_off[n + 1];
    float4 acc = make_float4(0.f, 0.f, 0.f, 0.f);
    for (int e = e0 + ep; e < e1; e += 2) {
        int s = __ldg(g_slot + e);
        float4 v = __ldg((const float4*)(g_z + (size_t)s * HIDDEN) + cg);
        acc.x += v.x; acc.y += v.y; acc.z += v.z; acc.w += v.w;
    }
    acc.x += __shfl_xor_sync(0xffffffffu, acc.x, 4);
    acc.y += __shfl_xor_sync(0xffffffffu, acc.y, 4);
    acc.z += __shfl_xor_sync(0xffffffffu, acc.z, 4);
    acc.w += __shfl_xor_sync(0xffffffffu, acc.w, 4);

    if (ep == 0) {
        float di = g_dinv[n];
        float4 bb = __ldg((const float4*)b1 + cg);
        float4 zn = *((const float4*)(g_z + (size_t)n * HIDDEN) + cg);
        float4 r;
        r.x = fmaxf(fmaf(acc.x + zn.x, di, bb.x), 0.f) * di;
        r.y = fmaxf(fmaf(acc.y + zn.y, di, bb.y), 0.f) * di;
        r.z = fmaxf(fmaf(acc.z + zn.z, di, bb.z), 0.f) * di;
        r.w = fmaxf(fmaf(acc.w + zn.w, di, bb.w), 0.f) * di;
        *((float4*)(g_h + (size_t)n * HIDDEN) + cg) = r;
    }
}

// ---------------- layer 2 gather + GEMM2 (fused) ----------------
__global__ __launch_bounds__(256) void k_gather2(const float* __restrict__ W2,
                                                 const float* __restrict__ b2,
                                                 float* __restrict__ out) {
    __shared__ __align__(16) float ws[HIDDEN * OUT_DIM];  // 4 KB
    ((float4*)ws)[threadIdx.x] = ((const float4*)W2)[threadIdx.x];  // 256 float4
    __syncthreads();

    int gw = (blockIdx.x * 256 + threadIdx.x) >> 5;
    int lane = threadIdx.x & 31;
    int ns = lane >> 3, ep = (lane >> 2) & 1, cg = lane & 3;
    int n = gw * 4 + ns;
    if (n >= N_NODES) return;

    int e0 = g_off[n], e1 = g_off[n + 1];
    float4 acc = make_float4(0.f, 0.f, 0.f, 0.f);
    for (int e = e0 + ep; e < e1; e += 2) {
        int s = __ldg(g_slot + e);
        float4 v = __ldg((const float4*)(g_h + (size_t)s * HIDDEN) + cg);
        acc.x += v.x; acc.y += v.y; acc.z += v.z; acc.w += v.w;
    }
    acc.x += __shfl_xor_sync(0xffffffffu, acc.x, 4);
    acc.y += __shfl_xor_sync(0xffffffffu, acc.y, 4);
    acc.z += __shfl_xor_sync(0xffffffffu, acc.z, 4);
    acc.w += __shfl_xor_sync(0xffffffffu, acc.w, 4);

    float di = g_dinv[n];
    float4 hn = *((const float4*)(g_h + (size_t)n * HIDDEN) + cg);
    float4 my;
    my.x = (acc.x + hn.x) * di;
    my.y = (acc.y + hn.y) * di;
    my.z = (acc.z + hn.z) * di;
    my.w = (acc.w + hn.w) * di;

    float hk[16];
    int base8 = lane & ~7;
#pragma unroll
    for (int q = 0; q < 4; q++) {
        int sl = base8 + q;
        hk[q * 4 + 0] = __shfl_sync(0xffffffffu, my.x, sl);
        hk[q * 4 + 1] = __shfl_sync(0xffffffffu, my.y, sl);
        hk[q * 4 + 2] = __shfl_sync(0xffffffffu, my.z, sl);
        hk[q * 4 + 3] = __shfl_sync(0xffffffffu, my.w, sl);
    }

    int oc = lane & 7;
    float4 o0 = make_float4(0.f, 0.f, 0.f, 0.f);
    float4 o1 = make_float4(0.f, 0.f, 0.f, 0.f);
#pragma unroll
    for (int k = 0; k < HIDDEN; k++) {
        float xv = hk[k];
        const float4* wr = (const float4*)(ws + k * OUT_DIM + oc * 8);
        float4 wa = wr[0], wb = wr[1];
        o0.x = fmaf(xv, wa.x, o0.x); o0.y = fmaf(xv, wa.y, o0.y);
        o0.z = fmaf(xv, wa.z, o0.z); o0.w = fmaf(xv, wa.w, o0.w);
        o1.x = fmaf(xv, wb.x, o1.x); o1.y = fmaf(xv, wb.y, o1.y);
        o1.z = fmaf(xv, wb.z, o1.z); o1.w = fmaf(xv, wb.w, o1.w);
    }

    const float4* bb = (const float4*)b2 + oc * 2;
    float4 ba = __ldg(bb), bc = __ldg(bb + 1);
    float4* O = (float4*)(out + (size_t)n * OUT_DIM) + oc * 2;
    O[0] = make_float4(o0.x + ba.x, o0.y + ba.y, o0.z + ba.z, o0.w + ba.w);
    O[1] = make_float4(o1.x + bc.x, o1.y + bc.y, o1.z + bc.z, o1.w + bc.w);
}

// ---------------- launch ----------------
extern "C" void kernel_launch(void* const* d_in, const int* in_sizes, int n_in,
                              void* d_out, int out_size) {
    const float* x = nullptr;
    const float* W1 = nullptr;
    const float* b1 = nullptr;
    const float* W2 = nullptr;
    const float* b2 = nullptr;
    const int* ei = nullptr;
    int E = 0;
    for (int i = 0; i < n_in; i++) {
        long long sz = in_sizes[i];
        if (sz == (long long)N_NODES * IN_DIM)      x  = (const float*)d_in[i];
        else if (sz == IN_DIM * HIDDEN)             W1 = (const float*)d_in[i];
        else if (sz == HIDDEN)                      b1 = (const float*)d_in[i];
        else if (sz == HIDDEN * OUT_DIM)            W2 = (const float*)d_in[i];
        else if (sz == OUT_DIM)                     b2 = (const float*)d_in[i];
        else { ei = (const int*)d_in[i]; E = (int)(sz / 2); }
    }
    const int* src = ei;
    const int* dst = ei + E;
    float* out = (float*)d_out;

    const int TB = 256;
    int E4 = E / 4;
    int grid_n  = (N_NODES + TB - 1) / TB;           // 391
    int grid_e4 = (E4 + 1 + TB - 1) / TB;
    int grid_g1 = (N_NODES + 255) / 256;             // 391
    int grid_gw = (N_NODES / 4 * 32 + TB - 1) / TB;  // 25000 warps -> 3125 blocks

    k_zero<<<grid_n, TB>>>();
    k_count<<<grid_e4, TB>>>(dst, E4, E);
    k_dinv<<<grid_n, TB>>>();
    k_gemm1<<<grid_g1, 128>>>(x, W1);      // 4th launch (profiled)
    k_bsum<<<NBLK, TB>>>();
    k_bscan<<<1, 512>>>();
    k_expand<<<NBLK, TB>>>();
    k_fill<<<grid_e4, TB>>>(src, dst, E4, E);
    k_gather1<<<grid_gw, TB>>>(b1);
    k_gather2<<<grid_gw, TB>>>(W2, b2, out);
}